// round 8
// baseline (speedup 1.0000x reference)
#include <cuda_runtime.h>
#include <math.h>

constexpr int B  = 2;
constexpr int C  = 64;
constexpr int H  = 180;
constexpr int W  = 360;
constexpr int HW = H * W;              // 64800
constexpr int Hp = H + 2;              // 182
constexpr int Wp = W + 2;              // 362
constexpr int NTILES = (B * HW) / 32;  // 4050 32-pixel tiles
constexpr int PBLK = 128;
constexpr int NPT = (NTILES + 3) / 4;  // 1013
constexpr int STATS_BLOCKS = 128;
constexpr float TWO_PI = 6.283185307179586f;

__device__ uint4 g_part[STATS_BLOCKS];

__device__ __forceinline__ unsigned fenc(float f) {
    unsigned u = __float_as_uint(f);
    return (u & 0x80000000u) ? ~u : (u | 0x80000000u);
}
__device__ __forceinline__ float fdec(unsigned e) {
    return __uint_as_float((e & 0x80000000u) ? (e ^ 0x80000000u) : ~e);
}

// ---- packed f32x2 helpers -------------------------------------------------
typedef unsigned long long ull;
__device__ __forceinline__ ull bcast2(float x) {
    ull r; asm("mov.b64 %0, {%1, %1};" : "=l"(r) : "f"(x)); return r;
}
__device__ __forceinline__ ull fma2(ull a, ull b, ull c) {
    ull d; asm("fma.rn.f32x2 %0, %1, %2, %3;" : "=l"(d) : "l"(a), "l"(b), "l"(c)); return d;
}

// ---------------------------------------------------------------------------
// Stats: one float4 per thread per array, per-block partials (no global atomics)
// ---------------------------------------------------------------------------
__global__ void stats_kernel(const float* __restrict__ lat,
                             const float* __restrict__ lon, int n)
{
    const int n4 = n >> 2;
    unsigned mnla = 0xFFFFFFFFu, mxla = 0u, mnlo = 0xFFFFFFFFu, mxlo = 0u;
    for (int i = blockIdx.x * blockDim.x + threadIdx.x; i < n4; i += gridDim.x * blockDim.x) {
        float4 a = __ldg((const float4*)lat + i);
        float4 o = __ldg((const float4*)lon + i);
        mnla = min(mnla, min(min(fenc(a.x), fenc(a.y)), min(fenc(a.z), fenc(a.w))));
        mxla = max(mxla, max(max(fenc(a.x), fenc(a.y)), max(fenc(a.z), fenc(a.w))));
        mnlo = min(mnlo, min(min(fenc(o.x), fenc(o.y)), min(fenc(o.z), fenc(o.w))));
        mxlo = max(mxlo, max(max(fenc(o.x), fenc(o.y)), max(fenc(o.z), fenc(o.w))));
    }
#pragma unroll
    for (int off = 16; off; off >>= 1) {
        mnla = min(mnla, __shfl_xor_sync(0xffffffffu, mnla, off));
        mxla = max(mxla, __shfl_xor_sync(0xffffffffu, mxla, off));
        mnlo = min(mnlo, __shfl_xor_sync(0xffffffffu, mnlo, off));
        mxlo = max(mxlo, __shfl_xor_sync(0xffffffffu, mxlo, off));
    }
    __shared__ unsigned s[4][8];
    int lane = threadIdx.x & 31, wid = threadIdx.x >> 5;
    if (lane == 0) { s[0][wid] = mnla; s[1][wid] = mxla; s[2][wid] = mnlo; s[3][wid] = mxlo; }
    __syncthreads();
    if (wid == 0) {
        mnla = (lane < 8) ? s[0][lane] : 0xFFFFFFFFu;
        mxla = (lane < 8) ? s[1][lane] : 0u;
        mnlo = (lane < 8) ? s[2][lane] : 0xFFFFFFFFu;
        mxlo = (lane < 8) ? s[3][lane] : 0u;
#pragma unroll
        for (int off = 4; off; off >>= 1) {
            mnla = min(mnla, __shfl_xor_sync(0xffffffffu, mnla, off));
            mxla = max(mxla, __shfl_xor_sync(0xffffffffu, mxla, off));
            mnlo = min(mnlo, __shfl_xor_sync(0xffffffffu, mnlo, off));
            mxlo = max(mxlo, __shfl_xor_sync(0xffffffffu, mxlo, off));
        }
        if (lane == 0) g_part[blockIdx.x] = make_uint4(mnla, mxla, mnlo, mxlo);
    }
}

// Bicubic weights (A = -0.75), matching reference exactly
__device__ __forceinline__ void cubic_w(float t, float w[4])
{
    const float A = -0.75f;
    float x;
    x = t + 1.0f;  w[0] = ((A * x - 5.0f * A) * x + 8.0f * A) * x - 4.0f * A;
    x = t;         w[1] = ((A + 2.0f) * x - (A + 3.0f)) * x * x + 1.0f;
    x = 1.0f - t;  w[2] = ((A + 2.0f) * x - (A + 3.0f)) * x * x + 1.0f;
    x = 2.0f - t;  w[3] = ((A * x - 5.0f * A) * x + 8.0f * A) * x - 4.0f * A;
}

// fast atan2, poly max err ~1e-6 rad
__device__ __forceinline__ float fast_atan2f(float y, float x)
{
    float ax = fabsf(x), ay = fabsf(y);
    float mx = fmaxf(ax, ay), mn = fminf(ax, ay);
    float a = (mx == 0.0f) ? 0.0f : __fdividef(mn, mx);
    float s = a * a;
    float r = fmaf(s, fmaf(s, fmaf(s, fmaf(s, fmaf(s, -0.0117212f, 0.05265332f),
                  -0.11643287f), 0.19354346f), -0.33262347f), 0.99997726f) * a;
    if (ay > ax)   r = 1.57079637f - r;
    if (x < 0.0f)  r = 3.14159274f - r;
    return (y < 0.0f) ? -r : r;
}

// ---------------------------------------------------------------------------
// Fused kernel. Block = 256 threads, covers 128 pixels x 32 output channels.
// ---------------------------------------------------------------------------
__global__ __launch_bounds__(256, 3)
void nsl_kernel(const float* __restrict__ hidden,
                const float* __restrict__ latg,
                const float* __restrict__ long_,
                const float* __restrict__ Wv,
                const float* __restrict__ bv,
                const float* __restrict__ dtp,
                float* __restrict__ out)
{
    __shared__ float pool[8192];                 // 32KB: sX[64][128] -> sU[32][128]+sV[32][128]
    __shared__ float s_sp[PBLK], s_cp[PBLK], s_lonp[PBLK];
    __shared__ float s_stats[4];

    const int tid   = threadIdx.x;
    const int chalf = blockIdx.x & 1;
    const int ptile = blockIdx.x >> 1;
    const int t0    = ptile * 4;
    const int co0   = chalf * 32;                // first output channel of this block
    const float dt  = dtp[0];

    // ---- phase 0: stage hidden tile sX[k][p], zero-fill invalid tiles
    for (int i = tid; i < 2048; i += 256) {
        int k = i >> 5, s = (i >> 3) & 3, f = i & 7;
        int t = t0 + s;
        float4 val = make_float4(0.f, 0.f, 0.f, 0.f);
        if (t < NTILES) {
            int b    = (t >= 2025) ? 1 : 0;
            int pixb = (t - b * 2025) * 32;
            val = *(const float4*)&hidden[((size_t)(b * C + k)) * HW + pixb + f * 4];
        }
        *(float4*)&pool[k * 128 + s * 32 + f * 4] = val;
    }

    // ---- per-pixel trig (warps 0-3) + stats reduce (warp 4, 128 partials)
    if (tid < PBLK) {
        int t = t0 + (tid >> 5);
        if (t < NTILES) {
            int b   = (t >= 2025) ? 1 : 0;
            int pix = (t - b * 2025) * 32 + (tid & 31);
            float la = latg[b * HW + pix];
            float lo = long_[b * HW + pix];
            float sp, cp;
            __sincosf(la, &sp, &cp);
            s_sp[tid] = sp; s_cp[tid] = cp; s_lonp[tid] = lo;
        }
    } else if (tid < PBLK + 32) {
        int l = tid - PBLK;
        unsigned mnla = 0xFFFFFFFFu, mxla = 0u, mnlo = 0xFFFFFFFFu, mxlo = 0u;
#pragma unroll
        for (int q = 0; q < STATS_BLOCKS / 32; q++) {
            uint4 v = g_part[q * 32 + l];
            mnla = min(mnla, v.x); mxla = max(mxla, v.y);
            mnlo = min(mnlo, v.z); mxlo = max(mxlo, v.w);
        }
#pragma unroll
        for (int off = 16; off; off >>= 1) {
            mnla = min(mnla, __shfl_xor_sync(0xffffffffu, mnla, off));
            mxla = max(mxla, __shfl_xor_sync(0xffffffffu, mxla, off));
            mnlo = min(mnlo, __shfl_xor_sync(0xffffffffu, mnlo, off));
            mxlo = max(mxlo, __shfl_xor_sync(0xffffffffu, mxlo, off));
        }
        if (l == 0) {
            s_stats[0] = fdec(mnla); s_stats[1] = fdec(mxla);
            s_stats[2] = fdec(mnlo); s_stats[3] = fdec(mxlo);
        }
    }
    __syncthreads();

    // ---- phase 1: projection with packed f32x2 FMA
    const int w  = tid >> 5;
    const int l  = tid & 31;
    const int c0 = co0 + w * 4;           // 4 output channels per warp
    const int p0 = l * 4;                 // 4 pixels per lane (2 f32x2 pairs)

    ull au2[4][2], av2[4][2];
#pragma unroll
    for (int cc = 0; cc < 4; cc++) {
        ull bu = bcast2(__ldg(&bv[c0 + cc]));
        ull bw = bcast2(__ldg(&bv[C + c0 + cc]));
        au2[cc][0] = bu; au2[cc][1] = bu;
        av2[cc][0] = bw; av2[cc][1] = bw;
    }

    for (int kk = 0; kk < 64; kk += 4) {
        ulonglong2 x0 = *(const ulonglong2*)&pool[(kk + 0) * 128 + p0];
        ulonglong2 x1 = *(const ulonglong2*)&pool[(kk + 1) * 128 + p0];
        ulonglong2 x2 = *(const ulonglong2*)&pool[(kk + 2) * 128 + p0];
        ulonglong2 x3 = *(const ulonglong2*)&pool[(kk + 3) * 128 + p0];
#pragma unroll
        for (int cc = 0; cc < 4; cc++) {
            float4 wu = __ldg((const float4*)&Wv[(c0 + cc) * 64 + kk]);
            float4 wv = __ldg((const float4*)&Wv[(C + c0 + cc) * 64 + kk]);
            ull b0 = bcast2(wu.x), b1 = bcast2(wu.y), b2 = bcast2(wu.z), b3 = bcast2(wu.w);
            au2[cc][0] = fma2(b0, x0.x, au2[cc][0]); au2[cc][1] = fma2(b0, x0.y, au2[cc][1]);
            au2[cc][0] = fma2(b1, x1.x, au2[cc][0]); au2[cc][1] = fma2(b1, x1.y, au2[cc][1]);
            au2[cc][0] = fma2(b2, x2.x, au2[cc][0]); au2[cc][1] = fma2(b2, x2.y, au2[cc][1]);
            au2[cc][0] = fma2(b3, x3.x, au2[cc][0]); au2[cc][1] = fma2(b3, x3.y, au2[cc][1]);
            ull d0 = bcast2(wv.x), d1 = bcast2(wv.y), d2 = bcast2(wv.z), d3 = bcast2(wv.w);
            av2[cc][0] = fma2(d0, x0.x, av2[cc][0]); av2[cc][1] = fma2(d0, x0.y, av2[cc][1]);
            av2[cc][0] = fma2(d1, x1.x, av2[cc][0]); av2[cc][1] = fma2(d1, x1.y, av2[cc][1]);
            av2[cc][0] = fma2(d2, x2.x, av2[cc][0]); av2[cc][1] = fma2(d2, x2.y, av2[cc][1]);
            av2[cc][0] = fma2(d3, x3.x, av2[cc][0]); av2[cc][1] = fma2(d3, x3.y, av2[cc][1]);
        }
    }
    __syncthreads();   // all sX reads done -> overlay u/v

    float* sU = pool;              // [32][128]
    float* sV = pool + 32 * 128;   // [32][128]
#pragma unroll
    for (int cc = 0; cc < 4; cc++) {
        *(ulonglong2*)&sU[(w * 4 + cc) * 128 + p0] = make_ulonglong2(au2[cc][0], au2[cc][1]);
        *(ulonglong2*)&sV[(w * 4 + cc) * 128 + p0] = make_ulonglong2(av2[cc][0], av2[cc][1]);
    }
    __syncthreads();

    // ---- phase 2: departure point + bicubic gather. thread: 1 pixel x 16 channels
    const int p    = tid & 127;
    const int half = tid >> 7;
    const int t    = t0 + (p >> 5);
    if (t >= NTILES) return;
    const int b   = (t >= 2025) ? 1 : 0;
    const int pix = (t - b * 2025) * 32 + (p & 31);

    const float sp = s_sp[p], cp = s_cp[p], lonp = s_lonp[p];

    const float minla = s_stats[0], maxla = s_stats[1];
    const float minlo = s_stats[2], maxlo = s_stats[3];
    const float gxsc = 2.0f / (maxlo - minlo);
    const float gysc = 2.0f / (maxla - minla);

    const float* basep = hidden + (size_t)b * C * HW;
    float* outp = out + ((size_t)b * C + co0) * HW + pix;

#pragma unroll 2
    for (int j = 0; j < 16; j++) {
        const int cl = half * 16 + j;                // local channel 0..31
        const float uu = sU[cl * 128 + p];
        const float vv = sV[cl * 128 + p];

        float lon_pr = -uu * dt;
        float lat_pr = -vv * dt;
        float slp, clp, slo, clo;
        __sincosf(lat_pr, &slp, &clp);
        __sincosf(lon_pr, &slo, &clo);

        float sin_lat = fmaf(slp, cp, clp * clo * sp);
        sin_lat = fminf(fmaxf(sin_lat, -1.0f + 1e-7f), 1.0f - 1e-7f);
        float lat = asinf(sin_lat);

        float num = clp * slo;
        float den = clp * clo * cp - slp * sp;
        float lx  = lonp + fast_atan2f(num, den) + TWO_PI;
        float lon = lx - floorf(lx * (1.0f / TWO_PI)) * TWO_PI;

        float gx = fmaf(lon - minlo, gxsc, -1.0f);
        float gy = fmaf(lat - minla, gysc, -1.0f);

        float tw = gx + 1.0f;
        tw -= floorf(tw * 0.5f) * 2.0f;
        gx = tw - 1.0f;

        bool left  = gx <= 0.0f;
        bool outer = fabsf(gy) > 1.0f;
        if (outer)           gx += left ? 1.0f : -1.0f;
        if (gy < -1.0f)      gy = -(2.0f + gy);
        else if (gy > 1.0f)  gy = 2.0f - gy;

        gx *= (float)W / (float)Wp;
        gy *= (float)H / (float)Hp;

        float ix = (gx + 1.0f) * (0.5f * (float)(Wp - 1));
        float iy = (gy + 1.0f) * (0.5f * (float)(Hp - 1));
        int ix0 = __float2int_rd(ix);
        int iy0 = __float2int_rd(iy);
        float tx = ix - (float)ix0;
        float ty = iy - (float)iy0;

        float wx[4], wy[4];
        cubic_w(tx, wx);
        cubic_w(ty, wy);

        int colp[4], colw[4];
#pragma unroll
        for (int ii = 0; ii < 4; ii++) {
            int xx  = min(max(ix0 + ii - 1, 0), Wp - 1);
            int col = (xx == 0) ? (W - 1) : ((xx == Wp - 1) ? 0 : (xx - 1));
            colp[ii] = col;
            int cw = col + W / 2; if (cw >= W) cw -= W;
            colw[ii] = cw;
        }

        const float* base = basep + (size_t)(co0 + cl) * HW;
        float acc = 0.0f;
#pragma unroll
        for (int jj = 0; jj < 4; jj++) {
            int  yy      = min(max(iy0 + jj - 1, 0), Hp - 1);
            bool wrapped = (yy == 0) || (yy == Hp - 1);
            int  row     = (yy == 0) ? 0 : ((yy == Hp - 1) ? (H - 1) : (yy - 1));
            const float* rp = base + row * W;
            int c0i = wrapped ? colw[0] : colp[0];
            int c1i = wrapped ? colw[1] : colp[1];
            int c2i = wrapped ? colw[2] : colp[2];
            int c3i = wrapped ? colw[3] : colp[3];
            float ra =          wx[0] * __ldg(&rp[c0i]);
            ra = fmaf(wx[1], __ldg(&rp[c1i]), ra);
            ra = fmaf(wx[2], __ldg(&rp[c2i]), ra);
            ra = fmaf(wx[3], __ldg(&rp[c3i]), ra);
            acc = fmaf(wy[jj], ra, acc);
        }
        outp[cl * HW] = acc;
    }
}

// ---------------------------------------------------------------------------
extern "C" void kernel_launch(void* const* d_in, const int* in_sizes, int n_in,
                              void* d_out, int out_size)
{
    const float* hidden = (const float*)d_in[0];
    const float* latg   = (const float*)d_in[1];
    const float* long_  = (const float*)d_in[2];
    const float* Wv     = (const float*)d_in[3];
    const float* bv     = (const float*)d_in[4];
    const float* dtp    = (const float*)d_in[5];
    float* out          = (float*)d_out;

    stats_kernel<<<STATS_BLOCKS, 256>>>(latg, long_, in_sizes[1]);
    nsl_kernel<<<2 * NPT, 256>>>(hidden, latg, long_, Wv, bv, dtp, out);
}

// round 11
// speedup vs baseline: 1.6467x; 1.6467x over previous
#include <cuda_runtime.h>
#include <math.h>

constexpr int B  = 2;
constexpr int C  = 64;
constexpr int H  = 180;
constexpr int W  = 360;
constexpr int HW = H * W;              // 64800
constexpr int Hp = H + 2;              // 182
constexpr int Wp = W + 2;              // 362
constexpr int NTILES = (B * HW) / 32;  // 4050 32-pixel tiles
constexpr int PBLK = 128;
constexpr int NPT = (NTILES + 3) / 4;  // 1013
constexpr int STATS_BLOCKS = 128;
constexpr float TWO_PI = 6.283185307179586f;

__device__ uint4 g_part[STATS_BLOCKS];

__device__ __forceinline__ unsigned fenc(float f) {
    unsigned u = __float_as_uint(f);
    return (u & 0x80000000u) ? ~u : (u | 0x80000000u);
}
__device__ __forceinline__ float fdec(unsigned e) {
    return __uint_as_float((e & 0x80000000u) ? (e ^ 0x80000000u) : ~e);
}

// ---------------------------------------------------------------------------
// Stats: one float4 per thread per array, per-block partials (no global atomics)
// ---------------------------------------------------------------------------
__global__ void stats_kernel(const float* __restrict__ lat,
                             const float* __restrict__ lon, int n)
{
    const int n4 = n >> 2;
    unsigned mnla = 0xFFFFFFFFu, mxla = 0u, mnlo = 0xFFFFFFFFu, mxlo = 0u;
    for (int i = blockIdx.x * blockDim.x + threadIdx.x; i < n4; i += gridDim.x * blockDim.x) {
        float4 a = __ldg((const float4*)lat + i);
        float4 o = __ldg((const float4*)lon + i);
        mnla = min(mnla, min(min(fenc(a.x), fenc(a.y)), min(fenc(a.z), fenc(a.w))));
        mxla = max(mxla, max(max(fenc(a.x), fenc(a.y)), max(fenc(a.z), fenc(a.w))));
        mnlo = min(mnlo, min(min(fenc(o.x), fenc(o.y)), min(fenc(o.z), fenc(o.w))));
        mxlo = max(mxlo, max(max(fenc(o.x), fenc(o.y)), max(fenc(o.z), fenc(o.w))));
    }
#pragma unroll
    for (int off = 16; off; off >>= 1) {
        mnla = min(mnla, __shfl_xor_sync(0xffffffffu, mnla, off));
        mxla = max(mxla, __shfl_xor_sync(0xffffffffu, mxla, off));
        mnlo = min(mnlo, __shfl_xor_sync(0xffffffffu, mnlo, off));
        mxlo = max(mxlo, __shfl_xor_sync(0xffffffffu, mxlo, off));
    }
    __shared__ unsigned s[4][8];
    int lane = threadIdx.x & 31, wid = threadIdx.x >> 5;
    if (lane == 0) { s[0][wid] = mnla; s[1][wid] = mxla; s[2][wid] = mnlo; s[3][wid] = mxlo; }
    __syncthreads();
    if (wid == 0) {
        mnla = (lane < 8) ? s[0][lane] : 0xFFFFFFFFu;
        mxla = (lane < 8) ? s[1][lane] : 0u;
        mnlo = (lane < 8) ? s[2][lane] : 0xFFFFFFFFu;
        mxlo = (lane < 8) ? s[3][lane] : 0u;
#pragma unroll
        for (int off = 4; off; off >>= 1) {
            mnla = min(mnla, __shfl_xor_sync(0xffffffffu, mnla, off));
            mxla = max(mxla, __shfl_xor_sync(0xffffffffu, mxla, off));
            mnlo = min(mnlo, __shfl_xor_sync(0xffffffffu, mnlo, off));
            mxlo = max(mxlo, __shfl_xor_sync(0xffffffffu, mxlo, off));
        }
        if (lane == 0) g_part[blockIdx.x] = make_uint4(mnla, mxla, mnlo, mxlo);
    }
}

// Bicubic weights (A = -0.75), matching reference exactly
__device__ __forceinline__ void cubic_w(float t, float w[4])
{
    const float A = -0.75f;
    float x;
    x = t + 1.0f;  w[0] = ((A * x - 5.0f * A) * x + 8.0f * A) * x - 4.0f * A;
    x = t;         w[1] = ((A + 2.0f) * x - (A + 3.0f)) * x * x + 1.0f;
    x = 1.0f - t;  w[2] = ((A + 2.0f) * x - (A + 3.0f)) * x * x + 1.0f;
    x = 2.0f - t;  w[3] = ((A * x - 5.0f * A) * x + 8.0f * A) * x - 4.0f * A;
}

// fast atan2, poly max err ~1e-6 rad
__device__ __forceinline__ float fast_atan2f(float y, float x)
{
    float ax = fabsf(x), ay = fabsf(y);
    float mx = fmaxf(ax, ay), mn = fminf(ax, ay);
    float a = (mx == 0.0f) ? 0.0f : __fdividef(mn, mx);
    float s = a * a;
    float r = fmaf(s, fmaf(s, fmaf(s, fmaf(s, fmaf(s, -0.0117212f, 0.05265332f),
                  -0.11643287f), 0.19354346f), -0.33262347f), 0.99997726f) * a;
    if (ay > ax)   r = 1.57079637f - r;
    if (x < 0.0f)  r = 3.14159274f - r;
    return (y < 0.0f) ? -r : r;
}

// ---------------------------------------------------------------------------
// Fused kernel. Block = 256 threads, covers 128 pixels x 32 output channels.
// ---------------------------------------------------------------------------
__global__ __launch_bounds__(256, 3)
void nsl_kernel(const float* __restrict__ hidden,
                const float* __restrict__ latg,
                const float* __restrict__ long_,
                const float* __restrict__ Wv,
                const float* __restrict__ bv,
                const float* __restrict__ dtp,
                float* __restrict__ out)
{
    __shared__ float pool[8192];                 // 32KB: sX[64][128] -> sU[32][128]+sV[32][128]
    __shared__ float s_sp[PBLK], s_cp[PBLK], s_lonp[PBLK];
    __shared__ float s_stats[4];

    const int tid   = threadIdx.x;
    const int chalf = blockIdx.x & 1;
    const int ptile = blockIdx.x >> 1;
    const int t0    = ptile * 4;
    const int co0   = chalf * 32;                // first output channel of this block
    const float dt  = dtp[0];

    // ---- phase 0: stage hidden tile sX[k][p], zero-fill invalid tiles
    for (int i = tid; i < 2048; i += 256) {
        int k = i >> 5, s = (i >> 3) & 3, f = i & 7;
        int t = t0 + s;
        float4 val = make_float4(0.f, 0.f, 0.f, 0.f);
        if (t < NTILES) {
            int b    = (t >= 2025) ? 1 : 0;
            int pixb = (t - b * 2025) * 32;
            val = *(const float4*)&hidden[((size_t)(b * C + k)) * HW + pixb + f * 4];
        }
        *(float4*)&pool[k * 128 + s * 32 + f * 4] = val;
    }

    // ---- per-pixel trig (warps 0-3) + stats reduce (warp 4, 128 partials)
    if (tid < PBLK) {
        int t = t0 + (tid >> 5);
        if (t < NTILES) {
            int b   = (t >= 2025) ? 1 : 0;
            int pix = (t - b * 2025) * 32 + (tid & 31);
            float la = latg[b * HW + pix];
            float lo = long_[b * HW + pix];
            float sp, cp;
            __sincosf(la, &sp, &cp);
            s_sp[tid] = sp; s_cp[tid] = cp; s_lonp[tid] = lo;
        }
    } else if (tid < PBLK + 32) {
        int l = tid - PBLK;
        unsigned mnla = 0xFFFFFFFFu, mxla = 0u, mnlo = 0xFFFFFFFFu, mxlo = 0u;
#pragma unroll
        for (int q = 0; q < STATS_BLOCKS / 32; q++) {
            uint4 v = g_part[q * 32 + l];
            mnla = min(mnla, v.x); mxla = max(mxla, v.y);
            mnlo = min(mnlo, v.z); mxlo = max(mxlo, v.w);
        }
#pragma unroll
        for (int off = 16; off; off >>= 1) {
            mnla = min(mnla, __shfl_xor_sync(0xffffffffu, mnla, off));
            mxla = max(mxla, __shfl_xor_sync(0xffffffffu, mxla, off));
            mnlo = min(mnlo, __shfl_xor_sync(0xffffffffu, mnlo, off));
            mxlo = max(mxlo, __shfl_xor_sync(0xffffffffu, mxlo, off));
        }
        if (l == 0) {
            s_stats[0] = fdec(mnla); s_stats[1] = fdec(mxla);
            s_stats[2] = fdec(mnlo); s_stats[3] = fdec(mxlo);
        }
    }
    __syncthreads();

    // ---- phase 1: projection. warp w: channels co0+w*4..+3; lane: 4 pixels
    const int w  = tid >> 5;
    const int l  = tid & 31;
    const int c0 = co0 + w * 4;
    const int p0 = l * 4;

    float au[4][4], av[4][4];
#pragma unroll
    for (int cc = 0; cc < 4; cc++) {
        float bu = __ldg(&bv[c0 + cc]);
        float bw = __ldg(&bv[C + c0 + cc]);
#pragma unroll
        for (int px = 0; px < 4; px++) { au[cc][px] = bu; av[cc][px] = bw; }
    }

    for (int kk = 0; kk < 64; kk += 4) {
        float x[4][4];
#pragma unroll
        for (int dk = 0; dk < 4; dk++) {
            float4 v = *(const float4*)&pool[(kk + dk) * 128 + p0];
            x[dk][0] = v.x; x[dk][1] = v.y; x[dk][2] = v.z; x[dk][3] = v.w;
        }
#pragma unroll
        for (int cc = 0; cc < 4; cc++) {
            int c = c0 + cc;
            float4 wu = __ldg((const float4*)&Wv[c * 64 + kk]);
            float4 wv = __ldg((const float4*)&Wv[(C + c) * 64 + kk]);
#pragma unroll
            for (int px = 0; px < 4; px++) {
                au[cc][px] = fmaf(wu.x, x[0][px], fmaf(wu.y, x[1][px],
                             fmaf(wu.z, x[2][px], fmaf(wu.w, x[3][px], au[cc][px]))));
                av[cc][px] = fmaf(wv.x, x[0][px], fmaf(wv.y, x[1][px],
                             fmaf(wv.z, x[2][px], fmaf(wv.w, x[3][px], av[cc][px]))));
            }
        }
    }
    __syncthreads();   // all sX reads done -> overlay u/v

    float* sU = pool;              // [32][128]
    float* sV = pool + 32 * 128;   // [32][128]
#pragma unroll
    for (int cc = 0; cc < 4; cc++) {
        *(float4*)&sU[(w * 4 + cc) * 128 + p0] = make_float4(au[cc][0], au[cc][1], au[cc][2], au[cc][3]);
        *(float4*)&sV[(w * 4 + cc) * 128 + p0] = make_float4(av[cc][0], av[cc][1], av[cc][2], av[cc][3]);
    }
    __syncthreads();

    // ---- phase 2: departure point + bicubic gather. thread: 1 pixel x 16 channels
    const int p    = tid & 127;
    const int half = tid >> 7;
    const int t    = t0 + (p >> 5);
    if (t >= NTILES) return;
    const int b   = (t >= 2025) ? 1 : 0;
    const int pix = (t - b * 2025) * 32 + (p & 31);

    const float sp = s_sp[p], cp = s_cp[p], lonp = s_lonp[p];

    const float minla = s_stats[0], maxla = s_stats[1];
    const float minlo = s_stats[2], maxlo = s_stats[3];
    const float gxsc = 2.0f / (maxlo - minlo);
    const float gysc = 2.0f / (maxla - minla);

    const float* basep = hidden + (size_t)b * C * HW;
    float* outp = out + ((size_t)b * C + co0) * HW + pix;

#pragma unroll 2
    for (int j = 0; j < 16; j++) {
        const int cl = half * 16 + j;                // local channel 0..31
        const float uu = sU[cl * 128 + p];
        const float vv = sV[cl * 128 + p];

        float lon_pr = -uu * dt;
        float lat_pr = -vv * dt;
        float slp, clp, slo, clo;
        __sincosf(lat_pr, &slp, &clp);
        __sincosf(lon_pr, &slo, &clo);

        float sin_lat = fmaf(slp, cp, clp * clo * sp);
        sin_lat = fminf(fmaxf(sin_lat, -1.0f + 1e-7f), 1.0f - 1e-7f);
        float lat = asinf(sin_lat);

        float num = clp * slo;
        float den = clp * clo * cp - slp * sp;
        float lx  = lonp + fast_atan2f(num, den) + TWO_PI;
        float lon = lx - floorf(lx * (1.0f / TWO_PI)) * TWO_PI;

        float gx = fmaf(lon - minlo, gxsc, -1.0f);
        float gy = fmaf(lat - minla, gysc, -1.0f);

        float tw = gx + 1.0f;
        tw -= floorf(tw * 0.5f) * 2.0f;
        gx = tw - 1.0f;

        bool left  = gx <= 0.0f;
        bool outer = fabsf(gy) > 1.0f;
        if (outer)           gx += left ? 1.0f : -1.0f;
        if (gy < -1.0f)      gy = -(2.0f + gy);
        else if (gy > 1.0f)  gy = 2.0f - gy;

        gx *= (float)W / (float)Wp;
        gy *= (float)H / (float)Hp;

        float ix = (gx + 1.0f) * (0.5f * (float)(Wp - 1));
        float iy = (gy + 1.0f) * (0.5f * (float)(Hp - 1));
        int ix0 = __float2int_rd(ix);
        int iy0 = __float2int_rd(iy);
        float tx = ix - (float)ix0;
        float ty = iy - (float)iy0;

        float wx[4], wy[4];
        cubic_w(tx, wx);
        cubic_w(ty, wy);

        int colp[4], colw[4];
#pragma unroll
        for (int ii = 0; ii < 4; ii++) {
            int xx  = min(max(ix0 + ii - 1, 0), Wp - 1);
            int col = (xx == 0) ? (W - 1) : ((xx == Wp - 1) ? 0 : (xx - 1));
            colp[ii] = col;
            int cw = col + W / 2; if (cw >= W) cw -= W;
            colw[ii] = cw;
        }

        const float* base = basep + (size_t)(co0 + cl) * HW;
        float acc = 0.0f;
#pragma unroll
        for (int jj = 0; jj < 4; jj++) {
            int  yy      = min(max(iy0 + jj - 1, 0), Hp - 1);
            bool wrapped = (yy == 0) || (yy == Hp - 1);
            int  row     = (yy == 0) ? 0 : ((yy == Hp - 1) ? (H - 1) : (yy - 1));
            const float* rp = base + row * W;
            int c0i = wrapped ? colw[0] : colp[0];
            int c1i = wrapped ? colw[1] : colp[1];
            int c2i = wrapped ? colw[2] : colp[2];
            int c3i = wrapped ? colw[3] : colp[3];
            float ra =          wx[0] * __ldg(&rp[c0i]);
            ra = fmaf(wx[1], __ldg(&rp[c1i]), ra);
            ra = fmaf(wx[2], __ldg(&rp[c2i]), ra);
            ra = fmaf(wx[3], __ldg(&rp[c3i]), ra);
            acc = fmaf(wy[jj], ra, acc);
        }
        outp[cl * HW] = acc;
    }
}

// ---------------------------------------------------------------------------
extern "C" void kernel_launch(void* const* d_in, const int* in_sizes, int n_in,
                              void* d_out, int out_size)
{
    const float* hidden = (const float*)d_in[0];
    const float* latg   = (const float*)d_in[1];
    const float* long_  = (const float*)d_in[2];
    const float* Wv     = (const float*)d_in[3];
    const float* bv     = (const float*)d_in[4];
    const float* dtp    = (const float*)d_in[5];
    float* out          = (float*)d_out;

    stats_kernel<<<STATS_BLOCKS, 256>>>(latg, long_, in_sizes[1]);
    nsl_kernel<<<2 * NPT, 256>>>(hidden, latg, long_, Wv, bv, dtp, out);
}